// round 13
// baseline (speedup 1.0000x reference)
#include <cuda_runtime.h>
#include <cuda_fp16.h>
#include <cstdint>

// FP4(E2M1) weight-only linear, fused persistent kernel:
//   phase 0: fp16 activation fragments (amax folded)
//   phase 1: fp16 mma.sync GEMM, 32 rows/warp; qweight via per-warp 4-stage
//            cp.async pipeline; bfrag+scales software-pipelined in registers
//   phase 2: split-K reduce + bias
// out[32,8192] = inp[32,8192] @ W^T + bias, W[n,k]=LUT(nib)*scales[n,k/16]*amax

#define TOKENS   32
#define NFEAT    8192
#define KFEAT    8192
#define NWIN     (KFEAT / 16)          // 512 mma k-steps
#define NMP      (NWIN / 2)            // 256 window-pairs
#define KSPLIT   8
#define MP_PER_CTA  (NMP / KSPLIT)     // 32
#define NCTAS    512
#define NST      4                     // cp.async stages (per warp)

__device__ uint4 g_bfrag[NMP * 4 * 32];             // fp16x2 x4 per [mp][g][lane] (2 MB)
__device__ float g_part[KSPLIT * TOKENS * NFEAT];   // split-K partials (8 MB)
__device__ unsigned g_cnt[2];                        // barrier counters (zero-init)
__device__ volatile unsigned g_phase[2];             // barrier phase flags

// ---------- helpers ----------
__device__ __forceinline__ uint32_t smem_u32(const void* p){
    uint32_t a;
    asm("{ .reg .u64 t; cvta.to.shared.u64 t, %1; cvt.u32.u64 %0, t; }" : "=r"(a) : "l"(p));
    return a;
}
#define CPA16(dst, src) asm volatile("cp.async.cg.shared.global [%0], [%1], 16;" :: "r"(dst), "l"(src))
#define CPA_COMMIT()    asm volatile("cp.async.commit_group;")
#define CPA_WAIT3()     asm volatile("cp.async.wait_group 3;")

__device__ __forceinline__ uint32_t dec16(uint32_t b){   // byte -> fp16x2 LUT pair (exact)
    uint32_t h = __byte_perm(0x3E3C3800u, 0x46444240u, b & 0x77u);
    uint32_t r = __byte_perm(h, 0u, 0x1404u);
    return r | ((b & 0x8u) << 12) | ((b & 0x80u) << 24);
}
__device__ __forceinline__ uint32_t hmul2(uint32_t a, uint32_t b){
    uint32_t r; asm("mul.rn.f16x2 %0, %1, %2;" : "=r"(r) : "r"(a), "r"(b)); return r;
}
__device__ __forceinline__ uint32_t dup_f16(float s){
    uint32_t r; asm("cvt.rn.f16x2.f32 %0, %1, %1;" : "=r"(r) : "f"(s)); return r;
}
__device__ __forceinline__ uint32_t pack_f16x2(float lo, float hi){
    uint32_t r; asm("cvt.rn.f16x2.f32 %0, %1, %2;" : "=r"(r) : "f"(hi), "f"(lo)); return r;
}
__device__ __forceinline__ void mma_acc(
    float& d0, float& d1, float& d2, float& d3,
    uint32_t a0, uint32_t a1, uint32_t a2, uint32_t a3,
    uint32_t b0, uint32_t b1)
{
    asm("mma.sync.aligned.m16n8k16.row.col.f32.f16.f16.f32 "
        "{%0,%1,%2,%3}, {%4,%5,%6,%7}, {%8,%9}, {%0,%1,%2,%3};"
        : "+f"(d0), "+f"(d1), "+f"(d2), "+f"(d3)
        : "r"(a0), "r"(a1), "r"(a2), "r"(a3), "r"(b0), "r"(b1));
}

// sense-reversing grid barrier; replay-safe (counter self-resets, phase toggles)
__device__ __forceinline__ void grid_barrier(int b){
    __syncthreads();
    if (threadIdx.x == 0){
        __threadfence();
        unsigned p = g_phase[b];
        unsigned arrived = atomicAdd(&g_cnt[b], 1u) + 1u;
        if (arrived == NCTAS){
            g_cnt[b] = 0u;
            __threadfence();
            g_phase[b] = p + 1u;
        } else {
            while (g_phase[b] == p) { __nanosleep(32); }
        }
    }
    __syncthreads();
    __threadfence();
}

// ---------------- fused persistent kernel ----------------
// grid (64, 8) = 512 CTAs, 128 thr, occ 4 (regs<=128, smem 32KB) -> 1 wave.
__global__ void __launch_bounds__(128, 4) fp4_fused_kernel(
    const int*   __restrict__ qw,       // [N, K/2] one packed byte per int32
    const float* __restrict__ scales,   // [N, K/16]
    const float* __restrict__ inp,      // [M, K]
    const float* __restrict__ amax,     // [1]
    const float* __restrict__ bias,     // [N]
    float*       __restrict__ out)      // [M, N]
{
    // per-warp private staging: [warp][stage][rowgroup j][lane] 16B
    __shared__ __align__(16) char qsm[4 * NST * 4 * 32 * 16];   // 32 KB

    const int tid = threadIdx.x, wid = tid >> 5, lane = tid & 31;
    const int bid = blockIdx.y * 64 + blockIdx.x;
    const int t   = bid * 128 + tid;                  // flat 0..65535

    // ========== phase 0: build fp16 B fragments (one uint2 per thread) ==========
    {
        int e = t >> 1, h = t & 1;
        int bl = e & 31, g = (e >> 5) & 3, mp = e >> 7;
        int bc = bl & 3, n = g * 8 + (bl >> 2);
        int k0 = 32 * mp + 8 * bc + 4 * h;
        const float am = __ldg(amax);
        float4 a = *reinterpret_cast<const float4*>(inp + (size_t)n * KFEAT + k0);
        reinterpret_cast<uint2*>(g_bfrag)[t] =
            make_uint2(pack_f16x2(a.x * am, a.y * am), pack_f16x2(a.z * am, a.w * am));
    }
    grid_barrier(0);

    // ========== phase 1: GEMM, 32 rows/warp, pipelined loads ==========
    {
        const int c  = lane & 3, rl = lane >> 2;
        const int r0 = blockIdx.x * 128 + wid * 32 + rl;   // rows r0,+8,+16,+24
        const int mpb = blockIdx.y * MP_PER_CTA;
        const bool hiblk = (lane & 2) != 0;

        float acc[4][8];
        #pragma unroll
        for (int g = 0; g < 4; ++g)
            #pragma unroll
            for (int j = 0; j < 8; ++j) acc[g][j] = 0.f;

        // cp.async sources: each lane's own uint4 (16B) per rowgroup per mp
        const char* qs0 = (const char*)(reinterpret_cast<const uint4*>(qw + (size_t)(r0     ) * (KFEAT / 2)) + c + (size_t)mpb * 4);
        const char* qs1 = (const char*)(reinterpret_cast<const uint4*>(qw + (size_t)(r0 +  8) * (KFEAT / 2)) + c + (size_t)mpb * 4);
        const char* qs2 = (const char*)(reinterpret_cast<const uint4*>(qw + (size_t)(r0 + 16) * (KFEAT / 2)) + c + (size_t)mpb * 4);
        const char* qs3 = (const char*)(reinterpret_cast<const uint4*>(qw + (size_t)(r0 + 24) * (KFEAT / 2)) + c + (size_t)mpb * 4);

        const float2* sr0 = reinterpret_cast<const float2*>(scales + (size_t)(r0     ) * NWIN) + mpb;
        const float2* sr1 = reinterpret_cast<const float2*>(scales + (size_t)(r0 +  8) * NWIN) + mpb;
        const float2* sr2 = reinterpret_cast<const float2*>(scales + (size_t)(r0 + 16) * NWIN) + mpb;
        const float2* sr3 = reinterpret_cast<const float2*>(scales + (size_t)(r0 + 24) * NWIN) + mpb;
        const uint4* bfp  = g_bfrag + (size_t)mpb * 128 + lane;   // [mp][g][lane]

        // per-warp SMEM base; lane slot within a stage
        const uint32_t warp_base = smem_u32(qsm) + (uint32_t)wid * (NST * 4 * 32 * 16);
        const uint32_t lane_off  = (uint32_t)lane * 16;

        // ---- cp.async prologue: stages for mp offsets 0..2 ----
        #pragma unroll
        for (int s = 0; s < NST - 1; ++s){
            const uint32_t so = warp_base + (uint32_t)s * (4 * 32 * 16);
            CPA16(so + 0 * 512 + lane_off, qs0 + (size_t)s * 64);
            CPA16(so + 1 * 512 + lane_off, qs1 + (size_t)s * 64);
            CPA16(so + 2 * 512 + lane_off, qs2 + (size_t)s * 64);
            CPA16(so + 3 * 512 + lane_off, qs3 + (size_t)s * 64);
            CPA_COMMIT();
        }

        // ---- register prefetch of iteration 0's bfrag + scales ----
        uint4 bfc[4];
        #pragma unroll
        for (int g = 0; g < 4; ++g) bfc[g] = __ldg(bfp + g * 32);
        float2 svc0 = __ldg(sr0), svc1 = __ldg(sr1), svc2 = __ldg(sr2), svc3 = __ldg(sr3);

        #pragma unroll 2
        for (int mpl = 0; mpl < MP_PER_CTA; ++mpl){
            // issue q stage mpl+3
            if (mpl + NST - 1 < MP_PER_CTA){
                const uint32_t so = warp_base + (uint32_t)((mpl + NST - 1) & (NST - 1)) * (4 * 32 * 16);
                CPA16(so + 0 * 512 + lane_off, qs0 + (size_t)(mpl + NST - 1) * 64);
                CPA16(so + 1 * 512 + lane_off, qs1 + (size_t)(mpl + NST - 1) * 64);
                CPA16(so + 2 * 512 + lane_off, qs2 + (size_t)(mpl + NST - 1) * 64);
                CPA16(so + 3 * 512 + lane_off, qs3 + (size_t)(mpl + NST - 1) * 64);
            }
            CPA_COMMIT();

            // prefetch NEXT iteration's bfrag + scales (clamped at tail)
            const int nx = (mpl + 1 < MP_PER_CTA) ? (mpl + 1) : mpl;
            uint4 bfn[4];
            #pragma unroll
            for (int g = 0; g < 4; ++g) bfn[g] = __ldg(bfp + (size_t)nx * 128 + g * 32);
            const float2 svn0 = __ldg(sr0 + nx);
            const float2 svn1 = __ldg(sr1 + nx);
            const float2 svn2 = __ldg(sr2 + nx);
            const float2 svn3 = __ldg(sr3 + nx);

            // current iteration's scale regs
            const uint32_t h0 = dup_f16(hiblk ? svc0.y : svc0.x);
            const uint32_t h1 = dup_f16(hiblk ? svc1.y : svc1.x);
            const uint32_t h2 = dup_f16(hiblk ? svc2.y : svc2.x);
            const uint32_t h3 = dup_f16(hiblk ? svc3.y : svc3.x);

            // wait for q stage mpl; each lane reads back its own bytes (no sync)
            CPA_WAIT3();
            const uint32_t so = warp_base + (uint32_t)(mpl & (NST - 1)) * (4 * 32 * 16);
            uint4 q0, q1, q2, q3;
            asm volatile("ld.shared.v4.u32 {%0,%1,%2,%3}, [%4];" : "=r"(q0.x),"=r"(q0.y),"=r"(q0.z),"=r"(q0.w) : "r"(so + 0 * 512 + lane_off));
            asm volatile("ld.shared.v4.u32 {%0,%1,%2,%3}, [%4];" : "=r"(q1.x),"=r"(q1.y),"=r"(q1.z),"=r"(q1.w) : "r"(so + 1 * 512 + lane_off));
            asm volatile("ld.shared.v4.u32 {%0,%1,%2,%3}, [%4];" : "=r"(q2.x),"=r"(q2.y),"=r"(q2.z),"=r"(q2.w) : "r"(so + 2 * 512 + lane_off));
            asm volatile("ld.shared.v4.u32 {%0,%1,%2,%3}, [%4];" : "=r"(q3.x),"=r"(q3.y),"=r"(q3.z),"=r"(q3.w) : "r"(so + 3 * 512 + lane_off));

            {   // e = 0 (k 0..15 of pair)
                const uint32_t a00 = hmul2(dec16(q0.x), h0), a02 = hmul2(dec16(q0.y), h0);
                const uint32_t a01 = hmul2(dec16(q1.x), h1), a03 = hmul2(dec16(q1.y), h1);
                const uint32_t a10 = hmul2(dec16(q2.x), h2), a12 = hmul2(dec16(q2.y), h2);
                const uint32_t a11 = hmul2(dec16(q3.x), h3), a13 = hmul2(dec16(q3.y), h3);
                #pragma unroll
                for (int g = 0; g < 4; ++g){
                    mma_acc(acc[g][0], acc[g][1], acc[g][2], acc[g][3],
                            a00, a01, a02, a03, bfc[g].x, bfc[g].y);
                    mma_acc(acc[g][4], acc[g][5], acc[g][6], acc[g][7],
                            a10, a11, a12, a13, bfc[g].x, bfc[g].y);
                }
            }
            {   // e = 1 (k 16..31 of pair)
                const uint32_t a00 = hmul2(dec16(q0.z), h0), a02 = hmul2(dec16(q0.w), h0);
                const uint32_t a01 = hmul2(dec16(q1.z), h1), a03 = hmul2(dec16(q1.w), h1);
                const uint32_t a10 = hmul2(dec16(q2.z), h2), a12 = hmul2(dec16(q2.w), h2);
                const uint32_t a11 = hmul2(dec16(q3.z), h3), a13 = hmul2(dec16(q3.w), h3);
                #pragma unroll
                for (int g = 0; g < 4; ++g){
                    mma_acc(acc[g][0], acc[g][1], acc[g][2], acc[g][3],
                            a00, a01, a02, a03, bfc[g].z, bfc[g].w);
                    mma_acc(acc[g][4], acc[g][5], acc[g][6], acc[g][7],
                            a10, a11, a12, a13, bfc[g].z, bfc[g].w);
                }
            }

            // rotate prefetched registers
            #pragma unroll
            for (int g = 0; g < 4; ++g) bfc[g] = bfn[g];
            svc0 = svn0; svc1 = svn1; svc2 = svn2; svc3 = svn3;
        }

        // write split-K partials: token cols g*8+2c, 2c+1 ; rows r0, +8, +16, +24
        float* base = g_part + (size_t)blockIdx.y * (TOKENS * NFEAT);
        #pragma unroll
        for (int g = 0; g < 4; ++g){
            const int t0c = g * 8 + 2 * c;
            base[(size_t)t0c       * NFEAT + r0     ] = acc[g][0];
            base[(size_t)(t0c + 1) * NFEAT + r0     ] = acc[g][1];
            base[(size_t)t0c       * NFEAT + r0 +  8] = acc[g][2];
            base[(size_t)(t0c + 1) * NFEAT + r0 +  8] = acc[g][3];
            base[(size_t)t0c       * NFEAT + r0 + 16] = acc[g][4];
            base[(size_t)(t0c + 1) * NFEAT + r0 + 16] = acc[g][5];
            base[(size_t)t0c       * NFEAT + r0 + 24] = acc[g][6];
            base[(size_t)(t0c + 1) * NFEAT + r0 + 24] = acc[g][7];
        }
    }
    grid_barrier(1);

    // ========== phase 2: split-K reduce + bias (one float4 per thread) ==========
    {
        const int i4 = t;
        const float4 b = *reinterpret_cast<const float4*>(bias + ((i4 * 4) & (NFEAT - 1)));
        float4 s = b;
        #pragma unroll
        for (int cp = 0; cp < KSPLIT; ++cp){
            const float4 v = *reinterpret_cast<const float4*>(
                g_part + (size_t)cp * (TOKENS * NFEAT) + (size_t)i4 * 4);
            s.x += v.x; s.y += v.y; s.z += v.z; s.w += v.w;
        }
        reinterpret_cast<float4*>(out)[i4] = s;
    }
}

extern "C" void kernel_launch(void* const* d_in, const int* in_sizes, int n_in,
                              void* d_out, int out_size)
{
    const float* inp    = (const float*)d_in[0];
    const int*   qw     = (const int*)  d_in[1];
    const float* scales = (const float*)d_in[2];
    const float* amax   = (const float*)d_in[3];
    const float* bias   = (const float*)d_in[4];
    float* out = (float*)d_out;

    dim3 grid(NFEAT / 128, KSPLIT);
    fp4_fused_kernel<<<grid, 128>>>(qw, scales, inp, amax, bias, out);
}

// round 14
// speedup vs baseline: 1.2266x; 1.2266x over previous
#include <cuda_runtime.h>
#include <cuda_fp16.h>
#include <cstdint>

// FP4(E2M1) weight-only linear via fp16 mma.sync.
// out[32,8192] = inp[32,8192] @ W^T + bias, W[n,k]=LUT(nib)*scales[n,k/16]*amax
// GEMM kernel: per-CTA SMEM staging of activation fragments (built in-CTA from
// inp, amax folded) and scales; main loop touches global ONLY for qweight
// (register-prefetched 1 iter ahead). KSPLIT=16 so the slices fit in 48 KB.

#define TOKENS   32
#define NFEAT    8192
#define KFEAT    8192
#define NWIN     (KFEAT / 16)          // 512 mma k-steps
#define NMP      (NWIN / 2)            // 256 window-pairs
#define KSPLIT   16
#define MP_PER_CTA  (NMP / KSPLIT)     // 16

__device__ float g_part[KSPLIT * TOKENS * NFEAT];   // split-K partials (16 MB)

// ---------- helpers ----------
__device__ __forceinline__ uint32_t dec16(uint32_t b){   // byte -> fp16x2 LUT pair (exact)
    uint32_t h = __byte_perm(0x3E3C3800u, 0x46444240u, b & 0x77u);
    uint32_t r = __byte_perm(h, 0u, 0x1404u);
    return r | ((b & 0x8u) << 12) | ((b & 0x80u) << 24);
}
__device__ __forceinline__ uint32_t hmul2(uint32_t a, uint32_t b){
    uint32_t r; asm("mul.rn.f16x2 %0, %1, %2;" : "=r"(r) : "r"(a), "r"(b)); return r;
}
__device__ __forceinline__ uint32_t dup_f16(float s){
    uint32_t r; asm("cvt.rn.f16x2.f32 %0, %1, %1;" : "=r"(r) : "f"(s)); return r;
}
__device__ __forceinline__ uint32_t pack_f16x2(float lo, float hi){
    uint32_t r; asm("cvt.rn.f16x2.f32 %0, %1, %2;" : "=r"(r) : "f"(hi), "f"(lo)); return r;
}
__device__ __forceinline__ void mma_acc(
    float& d0, float& d1, float& d2, float& d3,
    uint32_t a0, uint32_t a1, uint32_t a2, uint32_t a3,
    uint32_t b0, uint32_t b1)
{
    asm("mma.sync.aligned.m16n8k16.row.col.f32.f16.f16.f32 "
        "{%0,%1,%2,%3}, {%4,%5,%6,%7}, {%8,%9}, {%0,%1,%2,%3};"
        : "+f"(d0), "+f"(d1), "+f"(d2), "+f"(d3)
        : "r"(a0), "r"(a1), "r"(a2), "r"(a3), "r"(b0), "r"(b1));
}

// ---------------- GEMM kernel ----------------
// grid (64, 16) = 1024 CTAs, 128 thr (4 warps), occ 4 (48 KB smem, ~110 regs).
// Warp = 32 weight rows x 32 tokens; CTA = 128 rows x 512 k.
__global__ void __launch_bounds__(128, 4) fp4_gemm_kernel(
    const int*   __restrict__ qw,       // [N, K/2] one packed byte per int32
    const float* __restrict__ scales,   // [N, K/16]
    const float* __restrict__ inp,      // [M, K]
    const float* __restrict__ amax)     // [1]
{
    __shared__ __align__(16) uint4  sB[MP_PER_CTA * 128];   // 32 KB [mp][g*32+lane]
    __shared__ __align__(8)  float2 sS[MP_PER_CTA * 128];   // 16 KB [mp][local row]

    const int tid = threadIdx.x, wid = tid >> 5, lane = tid & 31;
    const int c  = lane & 3, rl = lane >> 2;
    const int nb0 = blockIdx.x * 128;
    const int mpb = blockIdx.y * MP_PER_CTA;
    const float am = __ldg(amax);

    // ---- stage activation fragments: thread owns (g=wid, lane), loops mp ----
    {
        const int n  = wid * 8 + rl;                 // token row 0..31
        const float* arow = inp + (size_t)n * KFEAT + 8 * c;
        #pragma unroll
        for (int i = 0; i < MP_PER_CTA; ++i){
            const int k0 = 32 * (mpb + i);
            const float4 a = *reinterpret_cast<const float4*>(arow + k0);
            const float4 b = *reinterpret_cast<const float4*>(arow + k0 + 4);
            sB[i * 128 + wid * 32 + lane] =
                make_uint4(pack_f16x2(a.x * am, a.y * am), pack_f16x2(a.z * am, a.w * am),
                           pack_f16x2(b.x * am, b.y * am), pack_f16x2(b.z * am, b.w * am));
        }
    }
    // ---- stage scales: thread tid owns global row nb0+tid ----
    {
        const float4* sp = reinterpret_cast<const float4*>(
            scales + (size_t)(nb0 + tid) * NWIN + mpb * 2);
        #pragma unroll
        for (int m4 = 0; m4 < MP_PER_CTA / 2; ++m4){
            const float4 v = __ldg(sp + m4);
            sS[(2 * m4    ) * 128 + tid] = make_float2(v.x, v.y);
            sS[(2 * m4 + 1) * 128 + tid] = make_float2(v.z, v.w);
        }
    }
    __syncthreads();

    // ---- main loop: only qweight touches global ----
    const int r0 = nb0 + wid * 32 + rl;              // rows r0,+8,+16,+24
    const int lrow = wid * 32 + rl;
    const bool hiblk = (lane & 2) != 0;

    float acc[4][8];
    #pragma unroll
    for (int g = 0; g < 4; ++g)
        #pragma unroll
        for (int j = 0; j < 8; ++j) acc[g][j] = 0.f;

    const uint4* qr0 = reinterpret_cast<const uint4*>(qw + (size_t)(r0     ) * (KFEAT / 2)) + c + (size_t)mpb * 4;
    const uint4* qr1 = reinterpret_cast<const uint4*>(qw + (size_t)(r0 +  8) * (KFEAT / 2)) + c + (size_t)mpb * 4;
    const uint4* qr2 = reinterpret_cast<const uint4*>(qw + (size_t)(r0 + 16) * (KFEAT / 2)) + c + (size_t)mpb * 4;
    const uint4* qr3 = reinterpret_cast<const uint4*>(qw + (size_t)(r0 + 24) * (KFEAT / 2)) + c + (size_t)mpb * 4;

    // register prefetch of iteration 0's q
    uint4 qc0 = __ldg(qr0), qc1 = __ldg(qr1), qc2 = __ldg(qr2), qc3 = __ldg(qr3);

    #pragma unroll 2
    for (int mpl = 0; mpl < MP_PER_CTA; ++mpl){
        // prefetch next iteration's q (clamped at tail)
        const int nx = (mpl + 1 < MP_PER_CTA) ? (mpl + 1) : mpl;
        const uint4 qn0 = __ldg(qr0 + nx * 4);
        const uint4 qn1 = __ldg(qr1 + nx * 4);
        const uint4 qn2 = __ldg(qr2 + nx * 4);
        const uint4 qn3 = __ldg(qr3 + nx * 4);

        // scales from SMEM (29-cyc LDS)
        const float2 s0 = sS[mpl * 128 + lrow     ];
        const float2 s1 = sS[mpl * 128 + lrow +  8];
        const float2 s2 = sS[mpl * 128 + lrow + 16];
        const float2 s3 = sS[mpl * 128 + lrow + 24];
        const uint32_t h0 = dup_f16(hiblk ? s0.y : s0.x);
        const uint32_t h1 = dup_f16(hiblk ? s1.y : s1.x);
        const uint32_t h2 = dup_f16(hiblk ? s2.y : s2.x);
        const uint32_t h3 = dup_f16(hiblk ? s3.y : s3.x);

        // activation fragments from SMEM
        uint4 bf[4];
        #pragma unroll
        for (int g = 0; g < 4; ++g)
            bf[g] = sB[mpl * 128 + g * 32 + lane];

        {   // e = 0 (k 0..15 of pair)
            const uint32_t a00 = hmul2(dec16(qc0.x), h0), a02 = hmul2(dec16(qc0.y), h0);
            const uint32_t a01 = hmul2(dec16(qc1.x), h1), a03 = hmul2(dec16(qc1.y), h1);
            const uint32_t a10 = hmul2(dec16(qc2.x), h2), a12 = hmul2(dec16(qc2.y), h2);
            const uint32_t a11 = hmul2(dec16(qc3.x), h3), a13 = hmul2(dec16(qc3.y), h3);
            #pragma unroll
            for (int g = 0; g < 4; ++g){
                mma_acc(acc[g][0], acc[g][1], acc[g][2], acc[g][3],
                        a00, a01, a02, a03, bf[g].x, bf[g].y);
                mma_acc(acc[g][4], acc[g][5], acc[g][6], acc[g][7],
                        a10, a11, a12, a13, bf[g].x, bf[g].y);
            }
        }
        {   // e = 1 (k 16..31 of pair)
            const uint32_t a00 = hmul2(dec16(qc0.z), h0), a02 = hmul2(dec16(qc0.w), h0);
            const uint32_t a01 = hmul2(dec16(qc1.z), h1), a03 = hmul2(dec16(qc1.w), h1);
            const uint32_t a10 = hmul2(dec16(qc2.z), h2), a12 = hmul2(dec16(qc2.w), h2);
            const uint32_t a11 = hmul2(dec16(qc3.z), h3), a13 = hmul2(dec16(qc3.w), h3);
            #pragma unroll
            for (int g = 0; g < 4; ++g){
                mma_acc(acc[g][0], acc[g][1], acc[g][2], acc[g][3],
                        a00, a01, a02, a03, bf[g].z, bf[g].w);
                mma_acc(acc[g][4], acc[g][5], acc[g][6], acc[g][7],
                        a10, a11, a12, a13, bf[g].z, bf[g].w);
            }
        }

        qc0 = qn0; qc1 = qn1; qc2 = qn2; qc3 = qn3;
    }

    // ---- write split-K partials: token cols g*8+2c, 2c+1 ; rows r0..+24 ----
    float* base = g_part + (size_t)blockIdx.y * (TOKENS * NFEAT);
    #pragma unroll
    for (int g = 0; g < 4; ++g){
        const int t0c = g * 8 + 2 * c;
        base[(size_t)t0c       * NFEAT + r0     ] = acc[g][0];
        base[(size_t)(t0c + 1) * NFEAT + r0     ] = acc[g][1];
        base[(size_t)t0c       * NFEAT + r0 +  8] = acc[g][2];
        base[(size_t)(t0c + 1) * NFEAT + r0 +  8] = acc[g][3];
        base[(size_t)t0c       * NFEAT + r0 + 16] = acc[g][4];
        base[(size_t)(t0c + 1) * NFEAT + r0 + 16] = acc[g][5];
        base[(size_t)t0c       * NFEAT + r0 + 24] = acc[g][6];
        base[(size_t)(t0c + 1) * NFEAT + r0 + 24] = acc[g][7];
    }
}

// ---------------- reduce split-K + bias ----------------
__global__ void reduce_kernel(const float* __restrict__ bias, float* __restrict__ out){
    int i4 = blockIdx.x * blockDim.x + threadIdx.x;
    if (i4 >= (TOKENS * NFEAT) / 4) return;
    const float4 b = *reinterpret_cast<const float4*>(bias + ((i4 * 4) & (NFEAT - 1)));
    float4 s = b;
    #pragma unroll
    for (int cp = 0; cp < KSPLIT; ++cp){
        const float4 v = *reinterpret_cast<const float4*>(
            g_part + (size_t)cp * (TOKENS * NFEAT) + (size_t)i4 * 4);
        s.x += v.x; s.y += v.y; s.z += v.z; s.w += v.w;
    }
    reinterpret_cast<float4*>(out)[i4] = s;
}

extern "C" void kernel_launch(void* const* d_in, const int* in_sizes, int n_in,
                              void* d_out, int out_size)
{
    const float* inp    = (const float*)d_in[0];
    const int*   qw     = (const int*)  d_in[1];
    const float* scales = (const float*)d_in[2];
    const float* amax   = (const float*)d_in[3];
    const float* bias   = (const float*)d_in[4];
    float* out = (float*)d_out;

    dim3 grid(NFEAT / 128, KSPLIT);
    fp4_gemm_kernel<<<grid, 128>>>(qw, scales, inp, amax);

    reduce_kernel<<<(TOKENS * NFEAT / 4 + 255) / 256, 256>>>(bias, out);
}

// round 15
// speedup vs baseline: 1.4136x; 1.1525x over previous
#include <cuda_runtime.h>
#include <cuda_fp16.h>
#include <cstdint>

// FP4(E2M1) weight-only linear via fp16 mma.sync.
// out[32,8192] = inp[32,8192] @ W^T + bias, W[n,k]=LUT(nib)*scales[n,k/16]*amax
// init kernel: out = bias.  GEMM: per-CTA SMEM staging of activation fragments
// (built in-CTA, amax folded) + scales; loop reads only qweight from global
// (register-prefetched); epilogue accumulates via atomicAdd (RED.F32) into the
// L2-resident output. No partial buffers, no reduce kernel.

#define TOKENS   32
#define NFEAT    8192
#define KFEAT    8192
#define NWIN     (KFEAT / 16)          // 512 mma k-steps
#define NMP      (NWIN / 2)            // 256 window-pairs
#define KSPLIT   16
#define MP_PER_CTA  (NMP / KSPLIT)     // 16

// ---------- helpers ----------
__device__ __forceinline__ uint32_t dec16(uint32_t b){   // byte -> fp16x2 LUT pair (exact)
    uint32_t h = __byte_perm(0x3E3C3800u, 0x46444240u, b & 0x77u);
    uint32_t r = __byte_perm(h, 0u, 0x1404u);
    return r | ((b & 0x8u) << 12) | ((b & 0x80u) << 24);
}
__device__ __forceinline__ uint32_t hmul2(uint32_t a, uint32_t b){
    uint32_t r; asm("mul.rn.f16x2 %0, %1, %2;" : "=r"(r) : "r"(a), "r"(b)); return r;
}
__device__ __forceinline__ uint32_t dup_f16(float s){
    uint32_t r; asm("cvt.rn.f16x2.f32 %0, %1, %1;" : "=r"(r) : "f"(s)); return r;
}
__device__ __forceinline__ uint32_t pack_f16x2(float lo, float hi){
    uint32_t r; asm("cvt.rn.f16x2.f32 %0, %1, %2;" : "=r"(r) : "f"(hi), "f"(lo)); return r;
}
__device__ __forceinline__ void mma_acc(
    float& d0, float& d1, float& d2, float& d3,
    uint32_t a0, uint32_t a1, uint32_t a2, uint32_t a3,
    uint32_t b0, uint32_t b1)
{
    asm("mma.sync.aligned.m16n8k16.row.col.f32.f16.f16.f32 "
        "{%0,%1,%2,%3}, {%4,%5,%6,%7}, {%8,%9}, {%0,%1,%2,%3};"
        : "+f"(d0), "+f"(d1), "+f"(d2), "+f"(d3)
        : "r"(a0), "r"(a1), "r"(a2), "r"(a3), "r"(b0), "r"(b1));
}

// ---------------- init: out = bias ----------------
__global__ void init_kernel(const float* __restrict__ bias, float* __restrict__ out){
    int i4 = blockIdx.x * blockDim.x + threadIdx.x;          // 0..65535
    if (i4 >= (TOKENS * NFEAT) / 4) return;
    const float4 b = *reinterpret_cast<const float4*>(bias + ((i4 * 4) & (NFEAT - 1)));
    reinterpret_cast<float4*>(out)[i4] = b;
}

// ---------------- GEMM kernel ----------------
// grid (64, 16) = 1024 CTAs, 128 thr (4 warps), occ 4 (48 KB smem).
// Warp = 32 weight rows x 32 tokens; CTA = 128 rows x 512 k.
__global__ void __launch_bounds__(128, 4) fp4_gemm_kernel(
    const int*   __restrict__ qw,       // [N, K/2] one packed byte per int32
    const float* __restrict__ scales,   // [N, K/16]
    const float* __restrict__ inp,      // [M, K]
    const float* __restrict__ amax,     // [1]
    float*       __restrict__ out)      // [M, N], pre-initialized with bias
{
    __shared__ __align__(16) uint4  sB[MP_PER_CTA * 128];   // 32 KB [mp][g*32+lane]
    __shared__ __align__(8)  float2 sS[MP_PER_CTA * 128];   // 16 KB [mp][local row]

    const int tid = threadIdx.x, wid = tid >> 5, lane = tid & 31;
    const int c  = lane & 3, rl = lane >> 2;
    const int nb0 = blockIdx.x * 128;
    const int mpb = blockIdx.y * MP_PER_CTA;
    const float am = __ldg(amax);

    // ---- stage activation fragments: thread owns (g=wid, lane), loops mp ----
    {
        const int n  = wid * 8 + rl;                 // token row 0..31
        const float* arow = inp + (size_t)n * KFEAT + 8 * c;
        #pragma unroll
        for (int i = 0; i < MP_PER_CTA; ++i){
            const int k0 = 32 * (mpb + i);
            const float4 a = *reinterpret_cast<const float4*>(arow + k0);
            const float4 b = *reinterpret_cast<const float4*>(arow + k0 + 4);
            sB[i * 128 + wid * 32 + lane] =
                make_uint4(pack_f16x2(a.x * am, a.y * am), pack_f16x2(a.z * am, a.w * am),
                           pack_f16x2(b.x * am, b.y * am), pack_f16x2(b.z * am, b.w * am));
        }
    }
    // ---- stage scales: thread tid owns global row nb0+tid ----
    {
        const float4* sp = reinterpret_cast<const float4*>(
            scales + (size_t)(nb0 + tid) * NWIN + mpb * 2);
        #pragma unroll
        for (int m4 = 0; m4 < MP_PER_CTA / 2; ++m4){
            const float4 v = __ldg(sp + m4);
            sS[(2 * m4    ) * 128 + tid] = make_float2(v.x, v.y);
            sS[(2 * m4 + 1) * 128 + tid] = make_float2(v.z, v.w);
        }
    }
    __syncthreads();

    // ---- main loop: only qweight touches global ----
    const int r0 = nb0 + wid * 32 + rl;              // rows r0,+8,+16,+24
    const int lrow = wid * 32 + rl;
    const bool hiblk = (lane & 2) != 0;

    float acc[4][8];
    #pragma unroll
    for (int g = 0; g < 4; ++g)
        #pragma unroll
        for (int j = 0; j < 8; ++j) acc[g][j] = 0.f;

    const uint4* qr0 = reinterpret_cast<const uint4*>(qw + (size_t)(r0     ) * (KFEAT / 2)) + c + (size_t)mpb * 4;
    const uint4* qr1 = reinterpret_cast<const uint4*>(qw + (size_t)(r0 +  8) * (KFEAT / 2)) + c + (size_t)mpb * 4;
    const uint4* qr2 = reinterpret_cast<const uint4*>(qw + (size_t)(r0 + 16) * (KFEAT / 2)) + c + (size_t)mpb * 4;
    const uint4* qr3 = reinterpret_cast<const uint4*>(qw + (size_t)(r0 + 24) * (KFEAT / 2)) + c + (size_t)mpb * 4;

    // register prefetch of iteration 0's q
    uint4 qc0 = __ldg(qr0), qc1 = __ldg(qr1), qc2 = __ldg(qr2), qc3 = __ldg(qr3);

    #pragma unroll 2
    for (int mpl = 0; mpl < MP_PER_CTA; ++mpl){
        // prefetch next iteration's q (clamped at tail)
        const int nx = (mpl + 1 < MP_PER_CTA) ? (mpl + 1) : mpl;
        const uint4 qn0 = __ldg(qr0 + nx * 4);
        const uint4 qn1 = __ldg(qr1 + nx * 4);
        const uint4 qn2 = __ldg(qr2 + nx * 4);
        const uint4 qn3 = __ldg(qr3 + nx * 4);

        // scales from SMEM
        const float2 s0 = sS[mpl * 128 + lrow     ];
        const float2 s1 = sS[mpl * 128 + lrow +  8];
        const float2 s2 = sS[mpl * 128 + lrow + 16];
        const float2 s3 = sS[mpl * 128 + lrow + 24];
        const uint32_t h0 = dup_f16(hiblk ? s0.y : s0.x);
        const uint32_t h1 = dup_f16(hiblk ? s1.y : s1.x);
        const uint32_t h2 = dup_f16(hiblk ? s2.y : s2.x);
        const uint32_t h3 = dup_f16(hiblk ? s3.y : s3.x);

        // activation fragments from SMEM
        uint4 bf[4];
        #pragma unroll
        for (int g = 0; g < 4; ++g)
            bf[g] = sB[mpl * 128 + g * 32 + lane];

        {   // e = 0 (k 0..15 of pair)
            const uint32_t a00 = hmul2(dec16(qc0.x), h0), a02 = hmul2(dec16(qc0.y), h0);
            const uint32_t a01 = hmul2(dec16(qc1.x), h1), a03 = hmul2(dec16(qc1.y), h1);
            const uint32_t a10 = hmul2(dec16(qc2.x), h2), a12 = hmul2(dec16(qc2.y), h2);
            const uint32_t a11 = hmul2(dec16(qc3.x), h3), a13 = hmul2(dec16(qc3.y), h3);
            #pragma unroll
            for (int g = 0; g < 4; ++g){
                mma_acc(acc[g][0], acc[g][1], acc[g][2], acc[g][3],
                        a00, a01, a02, a03, bf[g].x, bf[g].y);
                mma_acc(acc[g][4], acc[g][5], acc[g][6], acc[g][7],
                        a10, a11, a12, a13, bf[g].x, bf[g].y);
            }
        }
        {   // e = 1 (k 16..31 of pair)
            const uint32_t a00 = hmul2(dec16(qc0.z), h0), a02 = hmul2(dec16(qc0.w), h0);
            const uint32_t a01 = hmul2(dec16(qc1.z), h1), a03 = hmul2(dec16(qc1.w), h1);
            const uint32_t a10 = hmul2(dec16(qc2.z), h2), a12 = hmul2(dec16(qc2.w), h2);
            const uint32_t a11 = hmul2(dec16(qc3.z), h3), a13 = hmul2(dec16(qc3.w), h3);
            #pragma unroll
            for (int g = 0; g < 4; ++g){
                mma_acc(acc[g][0], acc[g][1], acc[g][2], acc[g][3],
                        a00, a01, a02, a03, bf[g].z, bf[g].w);
                mma_acc(acc[g][4], acc[g][5], acc[g][6], acc[g][7],
                        a10, a11, a12, a13, bf[g].z, bf[g].w);
            }
        }

        qc0 = qn0; qc1 = qn1; qc2 = qn2; qc3 = qn3;
    }

    // ---- epilogue: RED.F32 into L2-resident out (no partials, no reduce) ----
    #pragma unroll
    for (int g = 0; g < 4; ++g){
        const int t0c = g * 8 + 2 * c;
        atomicAdd(out + (size_t)t0c       * NFEAT + r0     , acc[g][0]);
        atomicAdd(out + (size_t)(t0c + 1) * NFEAT + r0     , acc[g][1]);
        atomicAdd(out + (size_t)t0c       * NFEAT + r0 +  8, acc[g][2]);
        atomicAdd(out + (size_t)(t0c + 1) * NFEAT + r0 +  8, acc[g][3]);
        atomicAdd(out + (size_t)t0c       * NFEAT + r0 + 16, acc[g][4]);
        atomicAdd(out + (size_t)(t0c + 1) * NFEAT + r0 + 16, acc[g][5]);
        atomicAdd(out + (size_t)t0c       * NFEAT + r0 + 24, acc[g][6]);
        atomicAdd(out + (size_t)(t0c + 1) * NFEAT + r0 + 24, acc[g][7]);
    }
}

extern "C" void kernel_launch(void* const* d_in, const int* in_sizes, int n_in,
                              void* d_out, int out_size)
{
    const float* inp    = (const float*)d_in[0];
    const int*   qw     = (const int*)  d_in[1];
    const float* scales = (const float*)d_in[2];
    const float* amax   = (const float*)d_in[3];
    const float* bias   = (const float*)d_in[4];
    float* out = (float*)d_out;

    init_kernel<<<(TOKENS * NFEAT / 4 + 255) / 256, 256>>>(bias, out);

    dim3 grid(NFEAT / 128, KSPLIT);
    fp4_gemm_kernel<<<grid, 128>>>(qw, scales, inp, amax, out);
}